// round 10
// baseline (speedup 1.0000x reference)
#include <cuda_runtime.h>
#include <cstdint>

// out[i,j] = swap_mask[i,j] ? x[i, perm[i,j]] : x[i,j]
// B=16384 rows, F=2048 cols (mask is int32).
// R8 structure (no SMEM/barrier, predicated L1 gather, .cs streaming) but
// one CTA = TWO rows: 12 front-batched independent loads per thread to
// deepen the per-warp L1tex/DRAM queue (MLP_eff 6 -> 12).

#define N_FEAT   2048
#define THREADS  256
#define ROWS_PER_CTA 2

__global__ __launch_bounds__(THREADS, 8)
void swap_corruption_kernel(const float* __restrict__ x,
                            const int* __restrict__ mask,
                            const int* __restrict__ perm,
                            float* __restrict__ out)
{
    const long long base0 = (long long)blockIdx.x * (N_FEAT * ROWS_PER_CTA);
    const long long base1 = base0 + N_FEAT;

    const float* __restrict__ xr0 = x + base0;
    const float* __restrict__ xr1 = x + base1;

    const float4* __restrict__ x40 = reinterpret_cast<const float4*>(xr0);
    const float4* __restrict__ x41 = reinterpret_cast<const float4*>(xr1);
    const int4*   __restrict__ p40 = reinterpret_cast<const int4*>(perm + base0);
    const int4*   __restrict__ p41 = reinterpret_cast<const int4*>(perm + base1);
    const int4*   __restrict__ m40 = reinterpret_cast<const int4*>(mask + base0);
    const int4*   __restrict__ m41 = reinterpret_cast<const int4*>(mask + base1);
    float4*       __restrict__ o40 = reinterpret_cast<float4*>(out + base0);
    float4*       __restrict__ o41 = reinterpret_cast<float4*>(out + base1);

    const int v0 = threadIdx.x;
    const int v1 = THREADS + threadIdx.x;

    // Front-batch ALL 12 independent loads (deep MLP before any dependence).
    const float4 xa0 = x40[v0];
    const float4 xb0 = x40[v1];
    const float4 xa1 = x41[v0];
    const float4 xb1 = x41[v1];
    const int4   ma0 = __ldcs(&m40[v0]);
    const int4   mb0 = __ldcs(&m40[v1]);
    const int4   ma1 = __ldcs(&m41[v0]);
    const int4   mb1 = __ldcs(&m41[v1]);
    const int4   pa0 = __ldcs(&p40[v0]);
    const int4   pb0 = __ldcs(&p40[v1]);
    const int4   pa1 = __ldcs(&p41[v0]);
    const int4   pb1 = __ldcs(&p41[v1]);

    // Row 0
    float4 r;
    r = xa0;
    if (ma0.x) r.x = __ldg(&xr0[pa0.x]);
    if (ma0.y) r.y = __ldg(&xr0[pa0.y]);
    if (ma0.z) r.z = __ldg(&xr0[pa0.z]);
    if (ma0.w) r.w = __ldg(&xr0[pa0.w]);
    __stcs(&o40[v0], r);

    r = xb0;
    if (mb0.x) r.x = __ldg(&xr0[pb0.x]);
    if (mb0.y) r.y = __ldg(&xr0[pb0.y]);
    if (mb0.z) r.z = __ldg(&xr0[pb0.z]);
    if (mb0.w) r.w = __ldg(&xr0[pb0.w]);
    __stcs(&o40[v1], r);

    // Row 1
    r = xa1;
    if (ma1.x) r.x = __ldg(&xr1[pa1.x]);
    if (ma1.y) r.y = __ldg(&xr1[pa1.y]);
    if (ma1.z) r.z = __ldg(&xr1[pa1.z]);
    if (ma1.w) r.w = __ldg(&xr1[pa1.w]);
    __stcs(&o41[v0], r);

    r = xb1;
    if (mb1.x) r.x = __ldg(&xr1[pb1.x]);
    if (mb1.y) r.y = __ldg(&xr1[pb1.y]);
    if (mb1.z) r.z = __ldg(&xr1[pb1.z]);
    if (mb1.w) r.w = __ldg(&xr1[pb1.w]);
    __stcs(&o41[v1], r);
}

extern "C" void kernel_launch(void* const* d_in, const int* in_sizes, int n_in,
                              void* d_out, int out_size)
{
    const float* x    = (const float*)d_in[0];
    const int*   mask = (const int*)d_in[1];
    const int*   perm = (const int*)d_in[2];
    float*       out  = (float*)d_out;

    const int batch = in_sizes[0] / N_FEAT;      // 16384
    const int grid  = batch / ROWS_PER_CTA;      // 8192
    swap_corruption_kernel<<<grid, THREADS>>>(x, mask, perm, out);
}

// round 14
// speedup vs baseline: 1.0221x; 1.0221x over previous
#include <cuda_runtime.h>
#include <cstdint>

// out[i,j] = swap_mask[i,j] ? x[i, perm[i,j]] : x[i,j]
// B=16384 rows, F=2048 cols (mask is int32).
// R8 structure (best: 70.3us kernel): no SMEM/barrier, predicated L1 gather,
// .cs streaming on perm/mask/out, default policy on x.
// Change vs R8: mask+perm loads issued FIRST so the dependent gather chain
// starts while x identity loads are still in flight (overlap the two chains).

#define N_FEAT   2048
#define THREADS  256

__global__ __launch_bounds__(THREADS, 8)
void swap_corruption_kernel(const float* __restrict__ x,
                            const int* __restrict__ mask,
                            const int* __restrict__ perm,
                            float* __restrict__ out)
{
    const long long base = (long long)blockIdx.x * N_FEAT;

    const float*  __restrict__ xrow = x + base;
    const float4* __restrict__ x4 = reinterpret_cast<const float4*>(xrow);
    const int4*   __restrict__ p4 = reinterpret_cast<const int4*>(perm + base);
    const int4*   __restrict__ m4 = reinterpret_cast<const int4*>(mask + base);
    float4*       __restrict__ o4 = reinterpret_cast<float4*>(out + base);

    const int v0 = threadIdx.x;
    const int v1 = THREADS + threadIdx.x;

    // Gather-dependence inputs first...
    const int4   m0 = __ldcs(&m4[v0]);
    const int4   m1 = __ldcs(&m4[v1]);
    const int4   p0 = __ldcs(&p4[v0]);
    const int4   p1 = __ldcs(&p4[v1]);
    // ...then identity inputs (default policy: lines reused by gather hits).
    const float4 xa = x4[v0];
    const float4 xb = x4[v1];

    // Predicated gathers: only mask-true lanes (~10%) issue the dependent LDG.
    float4 r0 = xa;
    if (m0.x) r0.x = __ldg(&xrow[p0.x]);
    if (m0.y) r0.y = __ldg(&xrow[p0.y]);
    if (m0.z) r0.z = __ldg(&xrow[p0.z]);
    if (m0.w) r0.w = __ldg(&xrow[p0.w]);

    float4 r1 = xb;
    if (m1.x) r1.x = __ldg(&xrow[p1.x]);
    if (m1.y) r1.y = __ldg(&xrow[p1.y]);
    if (m1.z) r1.z = __ldg(&xrow[p1.z]);
    if (m1.w) r1.w = __ldg(&xrow[p1.w]);

    __stcs(&o4[v0], r0);
    __stcs(&o4[v1], r1);
}

extern "C" void kernel_launch(void* const* d_in, const int* in_sizes, int n_in,
                              void* d_out, int out_size)
{
    const float* x    = (const float*)d_in[0];
    const int*   mask = (const int*)d_in[1];
    const int*   perm = (const int*)d_in[2];
    float*       out  = (float*)d_out;

    const int batch = in_sizes[0] / N_FEAT;      // 16384
    swap_corruption_kernel<<<batch, THREADS>>>(x, mask, perm, out);
}